// round 2
// baseline (speedup 1.0000x reference)
#include <cuda_runtime.h>
#include <cuda_bf16.h>
#include <cstdint>

// Problem constants (fixed shapes from the reference)
#define N_NODES 100000
#define HEADS   8

// Scratch: per-(node, head) sum of exp(e). 100000*8 floats = 3.2 MB (L2-resident).
__device__ float g_sums[N_NODES * HEADS];

__global__ void zero_sums_kernel(int n) {
    int i = blockIdx.x * blockDim.x + threadIdx.x;
    if (i < n) g_sums[i] = 0.0f;
}

// Pass 1: ex = exp(e); red-add ex into g_sums[dst]. One thread per edge.
// NOTE: harness narrows int64 indices to int32 -> read dst as const int*.
__global__ void scatter_sum_kernel(const float* __restrict__ e,
                                   const int* __restrict__ dst,
                                   int E) {
    int i = blockIdx.x * blockDim.x + threadIdx.x;
    if (i >= E) return;

    int d = dst[i];

    const float4* erow = reinterpret_cast<const float4*>(e + (size_t)i * HEADS);
    float4 a = erow[0];
    float4 b = erow[1];
    a.x = __expf(a.x); a.y = __expf(a.y); a.z = __expf(a.z); a.w = __expf(a.w);
    b.x = __expf(b.x); b.y = __expf(b.y); b.z = __expf(b.z); b.w = __expf(b.w);

    float* srow = g_sums + (size_t)d * HEADS;
    // Vector reductions (no return value) — 2 RED ops instead of 8 atomics.
    asm volatile("red.global.add.v4.f32 [%0], {%1, %2, %3, %4};"
                 :: "l"(srow), "f"(a.x), "f"(a.y), "f"(a.z), "f"(a.w) : "memory");
    asm volatile("red.global.add.v4.f32 [%0], {%1, %2, %3, %4};"
                 :: "l"(srow + 4), "f"(b.x), "f"(b.y), "f"(b.z), "f"(b.w) : "memory");
}

// Pass 2: out = exp(e) / (g_sums[dst] + eps). One thread per edge.
__global__ void normalize_kernel(const float* __restrict__ e,
                                 const int* __restrict__ dst,
                                 float* __restrict__ out,
                                 int E) {
    int i = blockIdx.x * blockDim.x + threadIdx.x;
    if (i >= E) return;

    int d = dst[i];

    const float4* erow = reinterpret_cast<const float4*>(e + (size_t)i * HEADS);
    float4 a = erow[0];
    float4 b = erow[1];
    a.x = __expf(a.x); a.y = __expf(a.y); a.z = __expf(a.z); a.w = __expf(a.w);
    b.x = __expf(b.x); b.y = __expf(b.y); b.z = __expf(b.z); b.w = __expf(b.w);

    const float4* srow = reinterpret_cast<const float4*>(g_sums + (size_t)d * HEADS);
    float4 s0 = srow[0];
    float4 s1 = srow[1];

    const float eps = 1e-16f;
    float4 o0, o1;
    o0.x = a.x / (s0.x + eps);
    o0.y = a.y / (s0.y + eps);
    o0.z = a.z / (s0.z + eps);
    o0.w = a.w / (s0.w + eps);
    o1.x = b.x / (s1.x + eps);
    o1.y = b.y / (s1.y + eps);
    o1.z = b.z / (s1.z + eps);
    o1.w = b.w / (s1.w + eps);

    float4* orow = reinterpret_cast<float4*>(out + (size_t)i * HEADS);
    orow[0] = o0;
    orow[1] = o1;
}

extern "C" void kernel_launch(void* const* d_in, const int* in_sizes, int n_in,
                              void* d_out, int out_size) {
    // Inputs: e [E, 8] float32, edge_index [2, E] (narrowed to int32 by harness)
    const float* e = (const float*)d_in[0];
    const int* edge_index = (const int*)d_in[1];
    int E = in_sizes[0] / HEADS;
    const int* dst = edge_index + (size_t)E;  // edge_index[1]

    float* out = (float*)d_out;

    const int T = 256;
    zero_sums_kernel<<<(N_NODES * HEADS + T - 1) / T, T>>>(N_NODES * HEADS);
    scatter_sum_kernel<<<(E + T - 1) / T, T>>>(e, dst, E);
    normalize_kernel<<<(E + T - 1) / T, T>>>(e, dst, out, E);
}